// round 2
// baseline (speedup 1.0000x reference)
#include <cuda_runtime.h>

// Problem constants
#define BB 2
#define HH 8
#define LL 512
#define DD 64
#define TI 4              // i rows per CTA
#define JT 32             // j tile
#define SCP 516           // padded score row stride (floats)
#define NTHR 256
#define TEMPINV 0.125f    // 1/sqrt(D) = 1/8

// Shared-memory layout (float offsets)
#define OFF_QS   0                       // qs[TI][HH][DD]            = 2048
#define OFF_SC   2048                    // sc[32][SCP]               = 16512
#define OFF_MASK (2048 + 32*SCP)         // mask flags [LL]           = 512
#define OFF_ST   (OFF_MASK + LL)         // staging union             = 25344
// phase1: kT[HH][DD][33] (16896) + adjT[TI][DD][33] (8448)
// phase2: vS[HH][JT][DD] (16384) + avS[TI][JT][DD]  (8192)
#define ST_UNION 25344
#define SMEM_FLOATS (OFF_ST + ST_UNION)  // 44416 floats = 177664 B

__global__ void __launch_bounds__(NTHR, 1)
relattn_kernel(const float* __restrict__ q, const float* __restrict__ k,
               const float* __restrict__ v, const float* __restrict__ adjk,
               const float* __restrict__ adjv, const int* __restrict__ mask,
               float* __restrict__ out, float* __restrict__ attn, int write_attn)
{
    extern __shared__ float sm[];
    const int bid = blockIdx.x;
    const int b   = bid / (LL / TI);
    const int i0  = (bid % (LL / TI)) * TI;
    const int tid = threadIdx.x;
    const int w    = tid >> 5;
    const int lane = tid & 31;

    float* qs   = sm + OFF_QS;
    float* sc   = sm + OFF_SC;
    float* mk   = sm + OFF_MASK;
    float* kT   = sm + OFF_ST;                  // phase1
    float* adjT = sm + OFF_ST + HH * DD * 33;   // phase1
    float* vS   = sm + OFF_ST;                  // phase2
    float* avS  = sm + OFF_ST + HH * JT * DD;   // phase2

    // ---------------- Phase 0: qs (scaled q) and mask flags ----------------
    for (int idx = tid; idx < TI * HH * DD; idx += NTHR) {
        int ti  = idx / (HH * DD);
        int rem = idx % (HH * DD);
        int h   = rem / DD;
        int d   = rem % DD;
        qs[idx] = q[((size_t)(b * HH + h) * LL + i0 + ti) * DD + d] * TEMPINV;
    }
    for (int j = tid; j < LL; j += NTHR)
        mk[j] = (mask[b * LL + j] != 0) ? 1.0f : 0.0f;

    // ---------------- Phase 1: scores sc[c][j], c = ti*8 + h ----------------
    {
        const int tp = w & 1, hp = w >> 1;
        const int ti0 = 2 * tp, h0 = 2 * hp;
        const float* qA = qs + (ti0 * HH + h0) * DD;
        const float* qB = qs + (ti0 * HH + h0 + 1) * DD;
        const float* qC = qs + ((ti0 + 1) * HH + h0) * DD;
        const float* qD = qs + ((ti0 + 1) * HH + h0 + 1) * DD;
        const int jj = lane;

        for (int j0 = 0; j0 < LL; j0 += JT) {
            __syncthreads();
            // stage k tile transposed: kT[(h*DD+d)*33 + jj]
            for (int f = tid; f < HH * JT * (DD / 4); f += NTHR) {
                int h   = f / (JT * (DD / 4));
                int r   = f % (JT * (DD / 4));
                int jjx = r / (DD / 4);
                int d4  = r % (DD / 4);
                float4 val = *reinterpret_cast<const float4*>(
                    &k[((size_t)(b * HH + h) * LL + j0 + jjx) * DD + d4 * 4]);
                float* base = kT + (h * DD + d4 * 4) * 33 + jjx;
                base[0] = val.x; base[33] = val.y; base[66] = val.z; base[99] = val.w;
            }
            // stage adj_k tile transposed: adjT[(ti*DD+d)*33 + jj]
            for (int f = tid; f < TI * JT * (DD / 4); f += NTHR) {
                int ti  = f / (JT * (DD / 4));
                int r   = f % (JT * (DD / 4));
                int jjx = r / (DD / 4);
                int d4  = r % (DD / 4);
                float4 val = *reinterpret_cast<const float4*>(
                    &adjk[((size_t)(b * LL + i0 + ti) * LL + j0 + jjx) * DD + d4 * 4]);
                float* base = adjT + (ti * DD + d4 * 4) * 33 + jjx;
                base[0] = val.x; base[33] = val.y; base[66] = val.z; base[99] = val.w;
            }
            __syncthreads();

            float a00 = 0.f, a01 = 0.f, a10 = 0.f, a11 = 0.f;
            const float* kp0 = kT + (h0 * DD) * 33 + jj;
            const float* kp1 = kT + ((h0 + 1) * DD) * 33 + jj;
            const float* bp0 = adjT + (ti0 * DD) * 33 + jj;
            const float* bp1 = adjT + ((ti0 + 1) * DD) * 33 + jj;
#pragma unroll 8
            for (int d = 0; d < DD; d++) {
                float k0 = kp0[d * 33], k1 = kp1[d * 33];
                float b0 = bp0[d * 33], b1 = bp1[d * 33];
                a00 += qA[d] * (k0 + b0);
                a01 += qB[d] * (k1 + b0);
                a10 += qC[d] * (k0 + b1);
                a11 += qD[d] * (k1 + b1);
            }
            sc[(ti0 * HH + h0) * SCP + j0 + jj]           = a00;
            sc[(ti0 * HH + h0 + 1) * SCP + j0 + jj]       = a01;
            sc[((ti0 + 1) * HH + h0) * SCP + j0 + jj]     = a10;
            sc[((ti0 + 1) * HH + h0 + 1) * SCP + j0 + jj] = a11;
        }
    }
    __syncthreads();

    // ---------------- Softmax (mask -> max -> exp -> norm), write attn ------
    for (int rr = 0; rr < 4; rr++) {
        int r  = w * 4 + rr;
        int ti = r / HH, h = r % HH;
        float* row = sc + r * SCP;
        float vals[16];
        float m = -3.4e38f;
#pragma unroll
        for (int t = 0; t < 16; t++) {
            int j = lane + t * 32;
            float s = row[j];
            s = (mk[j] != 0.0f) ? s : -10000.0f;
            vals[t] = s;
            m = fmaxf(m, s);
        }
#pragma unroll
        for (int o = 16; o > 0; o >>= 1)
            m = fmaxf(m, __shfl_xor_sync(0xffffffffu, m, o));
        float sum = 0.f;
#pragma unroll
        for (int t = 0; t < 16; t++) {
            float e = __expf(vals[t] - m);
            vals[t] = e;
            sum += e;
        }
#pragma unroll
        for (int o = 16; o > 0; o >>= 1)
            sum += __shfl_xor_sync(0xffffffffu, sum, o);
        float inv = 1.0f / sum;
        float* arow = attn + ((size_t)(b * HH + h) * LL + (i0 + ti)) * LL;
#pragma unroll
        for (int t = 0; t < 16; t++) {
            int j = lane + t * 32;
            float p = vals[t] * inv;
            row[j] = p;
            if (write_attn) arow[j] = p;
        }
    }
    __syncthreads();

    // ---------------- Phase 2: out[c][d] = sum_j p * (v + adj_v) ------------
    {
        const int ti    = w >> 1;
        const int hbase = (w & 1) * 4;
        const int l2    = lane * 2;
        float o0[4], o1[4];
#pragma unroll
        for (int cc = 0; cc < 4; cc++) { o0[cc] = 0.f; o1[cc] = 0.f; }

        for (int j0 = 0; j0 < LL; j0 += JT) {
            __syncthreads();
            // stage v tile (natural layout)
            for (int f = tid; f < HH * JT * (DD / 4); f += NTHR) {
                int h   = f / (JT * (DD / 4));
                int r   = f % (JT * (DD / 4));
                int jjx = r / (DD / 4);
                int d4  = r % (DD / 4);
                reinterpret_cast<float4*>(vS)[(h * JT + jjx) * (DD / 4) + d4] =
                    *reinterpret_cast<const float4*>(
                        &v[((size_t)(b * HH + h) * LL + j0 + jjx) * DD + d4 * 4]);
            }
            // stage adj_v tile (natural layout)
            for (int f = tid; f < TI * JT * (DD / 4); f += NTHR) {
                int ti2 = f / (JT * (DD / 4));
                int r   = f % (JT * (DD / 4));
                int jjx = r / (DD / 4);
                int d4  = r % (DD / 4);
                reinterpret_cast<float4*>(avS)[(ti2 * JT + jjx) * (DD / 4) + d4] =
                    *reinterpret_cast<const float4*>(
                        &adjv[((size_t)(b * LL + i0 + ti2) * LL + j0 + jjx) * DD + d4 * 4]);
            }
            __syncthreads();

            for (int jj = 0; jj < JT; jj++) {
                int j = j0 + jj;
                float2 av = *reinterpret_cast<const float2*>(&avS[(ti * JT + jj) * DD + l2]);
#pragma unroll
                for (int cc = 0; cc < 4; cc++) {
                    float p = sc[(ti * HH + hbase + cc) * SCP + j];  // warp-uniform broadcast
                    float2 vv = *reinterpret_cast<const float2*>(
                        &vS[((hbase + cc) * JT + jj) * DD + l2]);
                    o0[cc] += p * (vv.x + av.x);
                    o1[cc] += p * (vv.y + av.y);
                }
            }
        }
#pragma unroll
        for (int cc = 0; cc < 4; cc++) {
            float2 ov; ov.x = o0[cc]; ov.y = o1[cc];
            *reinterpret_cast<float2*>(
                &out[((size_t)(b * HH + hbase + cc) * LL + i0 + ti) * DD + l2]) = ov;
        }
    }
}

extern "C" void kernel_launch(void* const* d_in, const int* in_sizes, int n_in,
                              void* d_out, int out_size)
{
    const float* q    = (const float*)d_in[0];
    const float* k    = (const float*)d_in[1];
    const float* v    = (const float*)d_in[2];
    const float* adjk = (const float*)d_in[3];
    const float* adjv = (const float*)d_in[4];
    const int*   mask = (const int*)d_in[5];
    float* out = (float*)d_out;

    const int outElems  = BB * HH * LL * DD;   // 524288
    const int attnElems = BB * HH * LL * LL;   // 4194304
    float* attn;
    int write_attn;
    if (out_size >= outElems + attnElems) { attn = out + outElems; write_attn = 1; }
    else                                  { attn = out;            write_attn = 0; }

    cudaFuncSetAttribute(relattn_kernel,
                         cudaFuncAttributeMaxDynamicSharedMemorySize,
                         SMEM_FLOATS * 4);

    relattn_kernel<<<BB * (LL / TI), NTHR, SMEM_FLOATS * 4>>>(
        q, k, v, adjk, adjv, mask, out, attn, write_attn);
}

// round 3
// speedup vs baseline: 2.1436x; 2.1436x over previous
#include <cuda_runtime.h>

// Problem constants
#define BB 2
#define HH 8
#define LL 512
#define DD 64
#define TI 4               // i rows per CTA
#define NTHR 512
#define JT1 64             // phase-1 j tile
#define NT1 8              // phase-1 tiles (512/64)
#define JT2 32             // phase-2 j tile
#define NT2 16
#define PAD 68             // padded row stride (floats) for staged tiles
#define PST 34             // pS row stride
#define TEMPINV 0.125f

// Shared memory layout (float offsets)
#define OFF_QS   0                 // qs[32][64]            = 2048
#define OFF_MK   2048              // mask flags [512]
#define OFF_RED1 2560              // max partials [8][2][4] = 64
#define OFF_RED2 2624              // sum partials           = 64
#define OFF_U    2688              // union
// phase1: kS[8][64][PAD] = 34816 @U+0 ; adjS[4][64][PAD] = 17408 @U+34816  (end 52224)
// phase2: pS[512][PST]   = 17408 @U+0 ; vS[8][32][PAD] = 17408 @U+17408 ;
//         avS[4][32][PAD] = 8704 @U+34816 ; outred[4][32][64] = 8192 @U+43520 (end 51712)
#define U_KS    0
#define U_ADJ   34816
#define U_PS    0
#define U_VS    17408
#define U_AVS   34816
#define U_ORED  43520
#define SMEM_FLOATS (OFF_U + 52224)   // 54912 floats = 219648 bytes

__device__ __forceinline__ float warp_max(float x) {
#pragma unroll
    for (int o = 16; o; o >>= 1) x = fmaxf(x, __shfl_xor_sync(0xffffffffu, x, o));
    return x;
}
__device__ __forceinline__ float warp_sum(float x) {
#pragma unroll
    for (int o = 16; o; o >>= 1) x += __shfl_xor_sync(0xffffffffu, x, o);
    return x;
}

__global__ void __launch_bounds__(NTHR, 1)
relattn_kernel(const float* __restrict__ q, const float* __restrict__ k,
               const float* __restrict__ v, const float* __restrict__ adjk,
               const float* __restrict__ adjv, const int* __restrict__ mask,
               float* __restrict__ out, float* __restrict__ attn, int write_attn)
{
    extern __shared__ float sm[];
    const int bid  = blockIdx.x;
    const int b    = bid / (LL / TI);
    const int i0   = (bid % (LL / TI)) * TI;
    const int tid  = threadIdx.x;
    const int w    = tid >> 5;
    const int lane = tid & 31;

    float* qs = sm + OFF_QS;
    float* mk = sm + OFF_MK;
    float* r1 = sm + OFF_RED1;
    float* r2 = sm + OFF_RED2;
    float* U  = sm + OFF_U;

    // ---------------- Phase 0: qs and mask flags ----------------
    {
        // 2048 floats = 512 float4, one per thread
        int d4 = tid & 15, h = (tid >> 4) & 7, ti = tid >> 7;
        float4 val = *reinterpret_cast<const float4*>(
            &q[((size_t)(b * HH + h) * LL + i0 + ti) * DD + d4 * 4]);
        val.x *= TEMPINV; val.y *= TEMPINV; val.z *= TEMPINV; val.w *= TEMPINV;
        reinterpret_cast<float4*>(qs)[(ti * HH + h) * (DD / 4) + d4] = val;
        mk[tid] = (mask[b * LL + tid] != 0) ? 1.0f : 0.0f;
    }

    // ---------------- Phase 1: scores in registers ----------------
    // warp: bl = w>>1 (2x2 row block), jh = w&1 (j half of 64-tile)
    const int bl  = w >> 1;
    const int jh  = w & 1;
    const int ti0 = (bl >> 2) * 2;       // {0,2}
    const int h0  = (bl & 3) * 2;        // {0,2,4,6}
    const int jj1 = jh * 32 + lane;      // 0..63

    float s00[NT1], s01[NT1], s10[NT1], s11[NT1];

    const float4* qA = reinterpret_cast<const float4*>(qs + (ti0 * HH + h0) * DD);
    const float4* qB = reinterpret_cast<const float4*>(qs + (ti0 * HH + h0 + 1) * DD);
    const float4* qC = reinterpret_cast<const float4*>(qs + ((ti0 + 1) * HH + h0) * DD);
    const float4* qD = reinterpret_cast<const float4*>(qs + ((ti0 + 1) * HH + h0 + 1) * DD);

    float* kS   = U + U_KS;
    float* adjS = U + U_ADJ;

#pragma unroll 1
    for (int t = 0; t < NT1; t++) {
        const int j0 = t * JT1;
        __syncthreads();
        // stage k tile: [8 h][64 jj][PAD], natural layout, float4 coalesced
#pragma unroll
        for (int f = tid; f < 8 * 64 * 16; f += NTHR) {
            int d4 = f & 15, jjx = (f >> 4) & 63, h = f >> 10;
            float4 val = *reinterpret_cast<const float4*>(
                &k[((size_t)(b * HH + h) * LL + j0 + jjx) * DD + d4 * 4]);
            reinterpret_cast<float4*>(kS + (h * 64 + jjx) * PAD)[d4] = val;
        }
        // stage adj_k tile: [4 ti][64 jj][PAD]
#pragma unroll
        for (int f = tid; f < 4 * 64 * 16; f += NTHR) {
            int d4 = f & 15, jjx = (f >> 4) & 63, ti = f >> 10;
            float4 val = *reinterpret_cast<const float4*>(
                &adjk[((size_t)(b * LL + i0 + ti) * LL + j0 + jjx) * DD + d4 * 4]);
            reinterpret_cast<float4*>(adjS + (ti * 64 + jjx) * PAD)[d4] = val;
        }
        __syncthreads();

        const float4* kp0 = reinterpret_cast<const float4*>(kS + (h0 * 64 + jj1) * PAD);
        const float4* kp1 = reinterpret_cast<const float4*>(kS + ((h0 + 1) * 64 + jj1) * PAD);
        const float4* bp0 = reinterpret_cast<const float4*>(adjS + (ti0 * 64 + jj1) * PAD);
        const float4* bp1 = reinterpret_cast<const float4*>(adjS + ((ti0 + 1) * 64 + jj1) * PAD);

        float a00 = 0.f, a01 = 0.f, a10 = 0.f, a11 = 0.f;
#pragma unroll
        for (int d4 = 0; d4 < 16; d4++) {
            float4 k0 = kp0[d4], k1 = kp1[d4];
            float4 b0 = bp0[d4], b1 = bp1[d4];
            float4 qa = qA[d4], qb = qB[d4], qc = qC[d4], qd = qD[d4];
            a00 += qa.x * (k0.x + b0.x) + qa.y * (k0.y + b0.y)
                 + qa.z * (k0.z + b0.z) + qa.w * (k0.w + b0.w);
            a01 += qb.x * (k1.x + b0.x) + qb.y * (k1.y + b0.y)
                 + qb.z * (k1.z + b0.z) + qb.w * (k1.w + b0.w);
            a10 += qc.x * (k0.x + b1.x) + qc.y * (k0.y + b1.y)
                 + qc.z * (k0.z + b1.z) + qc.w * (k0.w + b1.w);
            a11 += qd.x * (k1.x + b1.x) + qd.y * (k1.y + b1.y)
                 + qd.z * (k1.z + b1.z) + qd.w * (k1.w + b1.w);
        }
        s00[t] = a00; s01[t] = a01; s10[t] = a10; s11[t] = a11;
    }

    // ---------------- Softmax on register scores ----------------
    float m00 = -3.4e38f, m01 = -3.4e38f, m10 = -3.4e38f, m11 = -3.4e38f;
#pragma unroll
    for (int t = 0; t < NT1; t++) {
        float msk = mk[t * JT1 + jj1];
        if (msk == 0.0f) { s00[t] = -10000.0f; s01[t] = -10000.0f;
                           s10[t] = -10000.0f; s11[t] = -10000.0f; }
        m00 = fmaxf(m00, s00[t]); m01 = fmaxf(m01, s01[t]);
        m10 = fmaxf(m10, s10[t]); m11 = fmaxf(m11, s11[t]);
    }
    m00 = warp_max(m00); m01 = warp_max(m01);
    m10 = warp_max(m10); m11 = warp_max(m11);
    if (lane == 0) {
        float* p = r1 + bl * 8 + jh * 4;
        p[0] = m00; p[1] = m01; p[2] = m10; p[3] = m11;
    }
    __syncthreads();
    {
        float* pa = r1 + bl * 8;
        m00 = fmaxf(pa[0], pa[4]); m01 = fmaxf(pa[1], pa[5]);
        m10 = fmaxf(pa[2], pa[6]); m11 = fmaxf(pa[3], pa[7]);
    }
    float sum00 = 0.f, sum01 = 0.f, sum10 = 0.f, sum11 = 0.f;
#pragma unroll
    for (int t = 0; t < NT1; t++) {
        s00[t] = __expf(s00[t] - m00); sum00 += s00[t];
        s01[t] = __expf(s01[t] - m01); sum01 += s01[t];
        s10[t] = __expf(s10[t] - m10); sum10 += s10[t];
        s11[t] = __expf(s11[t] - m11); sum11 += s11[t];
    }
    sum00 = warp_sum(sum00); sum01 = warp_sum(sum01);
    sum10 = warp_sum(sum10); sum11 = warp_sum(sum11);
    if (lane == 0) {
        float* p = r2 + bl * 8 + jh * 4;
        p[0] = sum00; p[1] = sum01; p[2] = sum10; p[3] = sum11;
    }
    __syncthreads();
    float i00, i01, i10, i11;
    {
        float* pa = r2 + bl * 8;
        i00 = 1.0f / (pa[0] + pa[4]); i01 = 1.0f / (pa[1] + pa[5]);
        i10 = 1.0f / (pa[2] + pa[6]); i11 = 1.0f / (pa[3] + pa[7]);
    }

    // write p to pS (smem) and attn (gmem). Safe: all kS/adjS reads completed
    // before the two syncs above.
    float* pS = U + U_PS;
    {
        const int r00 = ti0 * HH + h0, r01 = r00 + 1;
        const int r10 = (ti0 + 1) * HH + h0, r11 = r10 + 1;
        float* a00p = attn + (((size_t)(b * HH + h0) * LL) + i0 + ti0) * LL;
        float* a01p = attn + (((size_t)(b * HH + h0 + 1) * LL) + i0 + ti0) * LL;
        float* a10p = attn + (((size_t)(b * HH + h0) * LL) + i0 + ti0 + 1) * LL;
        float* a11p = attn + (((size_t)(b * HH + h0 + 1) * LL) + i0 + ti0 + 1) * LL;
#pragma unroll
        for (int t = 0; t < NT1; t++) {
            int j = t * JT1 + jj1;
            float p00 = s00[t] * i00, p01 = s01[t] * i01;
            float p10 = s10[t] * i10, p11 = s11[t] * i11;
            float* row = pS + j * PST;
            row[r00] = p00; row[r01] = p01; row[r10] = p10; row[r11] = p11;
            if (write_attn) {
                a00p[j] = p00; a01p[j] = p01; a10p[j] = p10; a11p[j] = p11;
            }
        }
    }

    // ---------------- Phase 2: out = p*(v + adj_v) ----------------
    // warp: rb = w>>2 -> h pair, js = w&3 -> j split within tile
    const int rb  = w >> 2;
    const int js  = w & 3;
    const int h0p = rb * 2;
    const int l2  = lane * 2;

    float* vS   = U + U_VS;
    float* avS  = U + U_AVS;
    float* ored = U + U_ORED;

    float2 o[4][2];
#pragma unroll
    for (int ti = 0; ti < 4; ti++)
#pragma unroll
        for (int hh = 0; hh < 2; hh++) { o[ti][hh].x = 0.f; o[ti][hh].y = 0.f; }

#pragma unroll 1
    for (int t2 = 0; t2 < NT2; t2++) {
        const int j0 = t2 * JT2;
        __syncthreads();
        // stage v tile: [8 h][32 jj][PAD]
#pragma unroll
        for (int f = tid; f < 8 * 32 * 16; f += NTHR) {
            int d4 = f & 15, jjx = (f >> 4) & 31, h = f >> 9;
            float4 val = *reinterpret_cast<const float4*>(
                &v[((size_t)(b * HH + h) * LL + j0 + jjx) * DD + d4 * 4]);
            reinterpret_cast<float4*>(vS + (h * 32 + jjx) * PAD)[d4] = val;
        }
        // stage adj_v tile: [4 ti][32 jj][PAD]
#pragma unroll
        for (int f = tid; f < 4 * 32 * 16; f += NTHR) {
            int d4 = f & 15, jjx = (f >> 4) & 31, ti = f >> 9;
            float4 val = *reinterpret_cast<const float4*>(
                &adjv[((size_t)(b * LL + i0 + ti) * LL + j0 + jjx) * DD + d4 * 4]);
            reinterpret_cast<float4*>(avS + (ti * 32 + jjx) * PAD)[d4] = val;
        }
        __syncthreads();

#pragma unroll
        for (int x = 0; x < 8; x++) {
            const int jj = js * 8 + x;
            const int j  = j0 + jj;
            float2 p0 = *reinterpret_cast<const float2*>(pS + j * PST + 0 * HH + h0p);
            float2 p1 = *reinterpret_cast<const float2*>(pS + j * PST + 1 * HH + h0p);
            float2 p2 = *reinterpret_cast<const float2*>(pS + j * PST + 2 * HH + h0p);
            float2 p3 = *reinterpret_cast<const float2*>(pS + j * PST + 3 * HH + h0p);
            float2 vv0 = *reinterpret_cast<const float2*>(vS + (h0p * 32 + jj) * PAD + l2);
            float2 vv1 = *reinterpret_cast<const float2*>(vS + ((h0p + 1) * 32 + jj) * PAD + l2);
            float2 av0 = *reinterpret_cast<const float2*>(avS + (0 * 32 + jj) * PAD + l2);
            float2 av1 = *reinterpret_cast<const float2*>(avS + (1 * 32 + jj) * PAD + l2);
            float2 av2 = *reinterpret_cast<const float2*>(avS + (2 * 32 + jj) * PAD + l2);
            float2 av3 = *reinterpret_cast<const float2*>(avS + (3 * 32 + jj) * PAD + l2);

            o[0][0].x += p0.x * (vv0.x + av0.x); o[0][0].y += p0.x * (vv0.y + av0.y);
            o[0][1].x += p0.y * (vv1.x + av0.x); o[0][1].y += p0.y * (vv1.y + av0.y);
            o[1][0].x += p1.x * (vv0.x + av1.x); o[1][0].y += p1.x * (vv0.y + av1.y);
            o[1][1].x += p1.y * (vv1.x + av1.x); o[1][1].y += p1.y * (vv1.y + av1.y);
            o[2][0].x += p2.x * (vv0.x + av2.x); o[2][0].y += p2.x * (vv0.y + av2.y);
            o[2][1].x += p2.y * (vv1.x + av2.x); o[2][1].y += p2.y * (vv1.y + av2.y);
            o[3][0].x += p3.x * (vv0.x + av3.x); o[3][0].y += p3.x * (vv0.y + av3.y);
            o[3][1].x += p3.y * (vv1.x + av3.x); o[3][1].y += p3.y * (vv1.y + av3.y);
        }
    }

    // partial writes: ored[js][row][64]
#pragma unroll
    for (int ti = 0; ti < 4; ti++)
#pragma unroll
        for (int hh = 0; hh < 2; hh++) {
            int row = ti * HH + h0p + hh;
            *reinterpret_cast<float2*>(ored + (js * 32 + row) * DD + l2) = o[ti][hh];
        }
    __syncthreads();

    // final reduce across 4 j-splits + gmem store: 2048 floats = 512 float4
    {
        int row = tid >> 4, d4 = tid & 15;
        float4 a = reinterpret_cast<const float4*>(ored + (0 * 32 + row) * DD)[d4];
        float4 bq = reinterpret_cast<const float4*>(ored + (1 * 32 + row) * DD)[d4];
        float4 c = reinterpret_cast<const float4*>(ored + (2 * 32 + row) * DD)[d4];
        float4 dq = reinterpret_cast<const float4*>(ored + (3 * 32 + row) * DD)[d4];
        float4 r;
        r.x = a.x + bq.x + c.x + dq.x;
        r.y = a.y + bq.y + c.y + dq.y;
        r.z = a.z + bq.z + c.z + dq.z;
        r.w = a.w + bq.w + c.w + dq.w;
        int ti = row / HH, h = row % HH;
        *reinterpret_cast<float4*>(
            &out[((size_t)(b * HH + h) * LL + i0 + ti) * DD + d4 * 4]) = r;
    }
}

extern "C" void kernel_launch(void* const* d_in, const int* in_sizes, int n_in,
                              void* d_out, int out_size)
{
    const float* q    = (const float*)d_in[0];
    const float* k    = (const float*)d_in[1];
    const float* v    = (const float*)d_in[2];
    const float* adjk = (const float*)d_in[3];
    const float* adjv = (const float*)d_in[4];
    const int*   mask = (const int*)d_in[5];
    float* out = (float*)d_out;

    const int outElems  = BB * HH * LL * DD;   // 524288
    const int attnElems = BB * HH * LL * LL;   // 4194304
    float* attn;
    int write_attn;
    if (out_size >= outElems + attnElems) { attn = out + outElems; write_attn = 1; }
    else                                  { attn = out;            write_attn = 0; }

    cudaFuncSetAttribute(relattn_kernel,
                         cudaFuncAttributeMaxDynamicSharedMemorySize,
                         SMEM_FLOATS * 4);

    relattn_kernel<<<BB * (LL / TI), NTHR, SMEM_FLOATS * 4>>>(
        q, k, v, adjk, adjv, mask, out, attn, write_attn);
}

// round 5
// speedup vs baseline: 2.7220x; 1.2698x over previous
#include <cuda_runtime.h>
#include <cstdint>

#define BB 2
#define HH 8
#define LL 512
#define DD 64
#define TI 4
#define NTHR 512
#define TEMPINV 0.125f

#define OUT_ELEMS  (BB*HH*LL*DD)
#define ATTN_ELEMS (BB*HH*LL*LL)

// 16 MB scratch for base scores qs@k^T ; 16 MB fallback attn buffer
__device__ float g_s0[ATTN_ELEMS];
__device__ float g_attn_fb[ATTN_ELEMS];

// ---------- main kernel smem layout (floats) ----------
#define OFF_QS   0                  // qs[4][8][64] = 2048
#define OFF_MK   2048               // 512
#define OFF_R1   2560               // 64
#define OFF_R2   2624               // 64
#define OFF_PS   2688               // pS[512][36] = 18432
#define OFF_BUF  21120              // double buffers
#define SM1_TILE (4*64*68)          // 17408 (phase1 adjk tile, PAD 68)
#define SM2_TILE (4*32*64)          // 8192  (phase2 adjv tile, no pad)
#define MAIN_SMEM_FLOATS (OFF_BUF + 2*SM1_TILE)   // 55936 -> 223744 B
#define PST 36

// ---------- PTX helpers ----------
__device__ __forceinline__ void cpa16(uint32_t dst, const void* src) {
    asm volatile("cp.async.cg.shared.global [%0], [%1], 16;" :: "r"(dst), "l"(src) : "memory");
}
#define CP_COMMIT asm volatile("cp.async.commit_group;" ::: "memory")
#define CP_WAIT1  asm volatile("cp.async.wait_group 1;" ::: "memory")
#define CP_WAIT0  asm volatile("cp.async.wait_group 0;" ::: "memory")

__device__ __forceinline__ void fma2(unsigned long long& d,
                                     unsigned long long a, unsigned long long b) {
    asm("fma.rn.f32x2 %0, %1, %2, %0;" : "+l"(d) : "l"(a), "l"(b));
}
__device__ __forceinline__ float hadd2(unsigned long long v) {
    float lo, hi;
    asm("mov.b64 {%0,%1}, %2;" : "=f"(lo), "=f"(hi) : "l"(v));
    return lo + hi;
}
__device__ __forceinline__ float warp_max(float x) {
#pragma unroll
    for (int o = 16; o; o >>= 1) x = fmaxf(x, __shfl_xor_sync(0xffffffffu, x, o));
    return x;
}
__device__ __forceinline__ float warp_sum(float x) {
#pragma unroll
    for (int o = 16; o; o >>= 1) x += __shfl_xor_sync(0xffffffffu, x, o);
    return x;
}

// =====================================================================
// Kernel 1: QK base scores. g_s0[bh,i,j] = (q/8)[bh,i,:] . k[bh,j,:]
// grid 256 = 16 bh x (4 itile x 4 jtile of 128x128), 256 thr, 8x8 micro
// =====================================================================
#define QK_PADI 132
#define QK_SMEM_FLOATS (2*64*QK_PADI)   // 16896 -> 67584 B

__global__ void __launch_bounds__(256, 2)
qk_kernel(const float* __restrict__ q, const float* __restrict__ k)
{
    extern __shared__ float smq[];
    float* qT = smq;                 // [64 d][132]
    float* kT = smq + 64 * QK_PADI;  // [64 d][132]
    const int bid = blockIdx.x;
    const int bh = bid >> 4;
    const int it = (bid >> 2) & 3, jt = bid & 3;
    const int i0 = it * 128, j0 = jt * 128;
    const int tid = threadIdx.x;

    const float* qb = q + ((size_t)bh * LL + i0) * DD;
    const float* kb = k + ((size_t)bh * LL + j0) * DD;
#pragma unroll
    for (int f = tid; f < 128 * 64; f += 256) {
        int i = f >> 6, d = f & 63;
        qT[d * QK_PADI + i] = qb[(size_t)i * DD + d] * TEMPINV;
        kT[d * QK_PADI + i] = kb[(size_t)i * DD + d];
    }
    __syncthreads();

    const int ty = tid >> 4, tx = tid & 15;
    const int il = ty * 8, jl = tx * 8;
    float acc[8][8];
#pragma unroll
    for (int r = 0; r < 8; r++)
#pragma unroll
        for (int c = 0; c < 8; c++) acc[r][c] = 0.f;

#pragma unroll 4
    for (int d = 0; d < 64; d++) {
        float4 a0 = *reinterpret_cast<const float4*>(qT + d * QK_PADI + il);
        float4 a1 = *reinterpret_cast<const float4*>(qT + d * QK_PADI + il + 4);
        float4 b0 = *reinterpret_cast<const float4*>(kT + d * QK_PADI + jl);
        float4 b1 = *reinterpret_cast<const float4*>(kT + d * QK_PADI + jl + 4);
        float a[8] = {a0.x,a0.y,a0.z,a0.w,a1.x,a1.y,a1.z,a1.w};
        float bb2[8] = {b0.x,b0.y,b0.z,b0.w,b1.x,b1.y,b1.z,b1.w};
#pragma unroll
        for (int r = 0; r < 8; r++)
#pragma unroll
            for (int c = 0; c < 8; c++) acc[r][c] += a[r] * bb2[c];
    }

#pragma unroll
    for (int r = 0; r < 8; r++) {
        float* dst = g_s0 + ((size_t)bh * LL + i0 + il + r) * LL + j0 + jl;
        float4 c0 = {acc[r][0], acc[r][1], acc[r][2], acc[r][3]};
        float4 c1 = {acc[r][4], acc[r][5], acc[r][6], acc[r][7]};
        *reinterpret_cast<float4*>(dst)     = c0;
        *reinterpret_cast<float4*>(dst + 4) = c1;
    }
}

// =====================================================================
// Kernel 2 (main): adj-score accumulation + softmax + adj_v weighted sum
// grid 256 = (b, i-tile of 4 rows), 512 thr
// =====================================================================
__global__ void __launch_bounds__(NTHR, 1)
main_kernel(const float* __restrict__ q, const float* __restrict__ adjk,
            const float* __restrict__ adjv, const int* __restrict__ mask,
            float* __restrict__ out, float* __restrict__ attn_ext, int write_ext)
{
    extern __shared__ float sm[];
    float* attn = write_ext ? attn_ext : g_attn_fb;

    const int bid  = blockIdx.x;
    const int b    = bid / (LL / TI);
    const int i0   = (bid % (LL / TI)) * TI;
    const int tid  = threadIdx.x;
    const int w    = tid >> 5;
    const int lane = tid & 31;

    float* qs = sm + OFF_QS;
    float* mk = sm + OFF_MK;
    float* r1 = sm + OFF_R1;
    float* r2 = sm + OFF_R2;
    float* pS = sm + OFF_PS;
    const uint32_t smemU = (uint32_t)__cvta_generic_to_shared(sm);

    // ---- phase 0: qs (scaled q) + mask flags ----
    {
        int d4 = tid & 15, h = (tid >> 4) & 7, ti = tid >> 7;
        float4 val = *reinterpret_cast<const float4*>(
            &q[((size_t)(b * HH + h) * LL + i0 + ti) * DD + d4 * 4]);
        val.x *= TEMPINV; val.y *= TEMPINV; val.z *= TEMPINV; val.w *= TEMPINV;
        reinterpret_cast<float4*>(qs)[(ti * HH + h) * (DD / 4) + d4] = val;
        mk[tid] = (mask[b * LL + tid] != 0) ? 1.0f : 0.0f;
    }

    // warp mapping phase 1: ti, jh (j half of 64), hg (head group of 4)
    const int ti  = w >> 2;
    const int sub = w & 3;
    const int jh  = sub >> 1;
    const int hg  = sub & 1;
    const int h0  = hg * 4;
    const int jj  = jh * 32 + lane;          // 0..63 within tile
    const int rbase = ti * HH + h0;          // row 0..31

    const float* adjk_b = adjk + ((size_t)(b * LL + i0) * LL) * DD;
    const float* adjv_b = adjv + ((size_t)(b * LL + i0) * LL) * DD;

    // prologue: stage phase-1 tile 0
    {
        const float* srcb = adjk_b;   // j0 = 0
#pragma unroll
        for (int s2 = 0; s2 < 8; s2++) {
            int f = tid + s2 * NTHR;
            int d4 = f & 15, jjx = (f >> 4) & 63, ti2 = f >> 10;
            cpa16(smemU + (uint32_t)(OFF_BUF + (ti2 * 64 + jjx) * 68 + d4 * 4) * 4,
                  srcb + (size_t)ti2 * (LL * DD) + (size_t)jjx * DD + d4 * 4);
        }
        CP_COMMIT;
    }

    // init scores from g_s0
    float s[4][8];
#pragma unroll
    for (int hh = 0; hh < 4; hh++)
#pragma unroll
        for (int t = 0; t < 8; t++)
            s[hh][t] = g_s0[((size_t)(b * HH + h0 + hh) * LL + i0 + ti) * LL + t * 64 + jj];

    // ---- phase 1: 8 tiles of 64 j, double-buffered ----
#pragma unroll
    for (int t = 0; t < 8; t++) {
        if (t < 7) {
            const float* srcb = adjk_b + (size_t)(t + 1) * 64 * DD;
            const int base = OFF_BUF + ((t + 1) & 1) * SM1_TILE;
#pragma unroll
            for (int s2 = 0; s2 < 8; s2++) {
                int f = tid + s2 * NTHR;
                int d4 = f & 15, jjx = (f >> 4) & 63, ti2 = f >> 10;
                cpa16(smemU + (uint32_t)(base + (ti2 * 64 + jjx) * 68 + d4 * 4) * 4,
                      srcb + (size_t)ti2 * (LL * DD) + (size_t)jjx * DD + d4 * 4);
            }
            CP_COMMIT;
            CP_WAIT1;
        } else {
            CP_WAIT0;
        }
        __syncthreads();

        const float* bufp = sm + OFF_BUF + (t & 1) * SM1_TILE;
        const ulonglong2* ap = reinterpret_cast<const ulonglong2*>(bufp + (ti * 64 + jj) * 68);
        const ulonglong2* q0 = reinterpret_cast<const ulonglong2*>(qs + (rbase + 0) * DD);
        const ulonglong2* q1 = reinterpret_cast<const ulonglong2*>(qs + (rbase + 1) * DD);
        const ulonglong2* q2 = reinterpret_cast<const ulonglong2*>(qs + (rbase + 2) * DD);
        const ulonglong2* q3 = reinterpret_cast<const ulonglong2*>(qs + (rbase + 3) * DD);
        unsigned long long a0 = 0ull, a1 = 0ull, a2 = 0ull, a3 = 0ull;
#pragma unroll
        for (int d4 = 0; d4 < 16; d4++) {
            ulonglong2 ad = ap[d4];
            ulonglong2 v0 = q0[d4]; fma2(a0, v0.x, ad.x); fma2(a0, v0.y, ad.y);
            ulonglong2 v1 = q1[d4]; fma2(a1, v1.x, ad.x); fma2(a1, v1.y, ad.y);
            ulonglong2 v2 = q2[d4]; fma2(a2, v2.x, ad.x); fma2(a2, v2.y, ad.y);
            ulonglong2 v3 = q3[d4]; fma2(a3, v3.x, ad.x); fma2(a3, v3.y, ad.y);
        }
        s[0][t] += hadd2(a0); s[1][t] += hadd2(a1);
        s[2][t] += hadd2(a2); s[3][t] += hadd2(a3);
        __syncthreads();
    }

    // prologue: stage phase-2 tile 0 (phase-1 buffers are dead now)
#pragma unroll
    for (int s2 = 0; s2 < 4; s2++) {
        int f = tid + s2 * NTHR;
        int d4 = f & 15, jx = (f >> 4) & 31, ti2 = f >> 9;
        cpa16(smemU + (uint32_t)(OFF_BUF + (ti2 * 32 + jx) * 64 + d4 * 4) * 4,
              adjv_b + (size_t)ti2 * (LL * DD) + (size_t)jx * DD + d4 * 4);
    }
    CP_COMMIT;

    // ---- softmax (mask -> max -> exp -> norm) ----
    float m[4] = {-3.4e38f, -3.4e38f, -3.4e38f, -3.4e38f};
#pragma unroll
    for (int t = 0; t < 8; t++) {
        bool live = mk[t * 64 + jj] != 0.0f;
#pragma unroll
        for (int hh = 0; hh < 4; hh++) {
            float x = live ? s[hh][t] : -10000.0f;
            s[hh][t] = x;
            m[hh] = fmaxf(m[hh], x);
        }
    }
#pragma unroll
    for (int hh = 0; hh < 4; hh++) m[hh] = warp_max(m[hh]);
    if (lane == 0) {
#pragma unroll
        for (int hh = 0; hh < 4; hh++) r1[(rbase + hh) * 2 + jh] = m[hh];
    }
    __syncthreads();
#pragma unroll
    for (int hh = 0; hh < 4; hh++)
        m[hh] = fmaxf(r1[(rbase + hh) * 2], r1[(rbase + hh) * 2 + 1]);

    float sum[4] = {0.f, 0.f, 0.f, 0.f};
#pragma unroll
    for (int t = 0; t < 8; t++)
#pragma unroll
        for (int hh = 0; hh < 4; hh++) {
            float e = __expf(s[hh][t] - m[hh]);
            s[hh][t] = e;
            sum[hh] += e;
        }
#pragma unroll
    for (int hh = 0; hh < 4; hh++) sum[hh] = warp_sum(sum[hh]);
    if (lane == 0) {
#pragma unroll
        for (int hh = 0; hh < 4; hh++) r2[(rbase + hh) * 2 + jh] = sum[hh];
    }
    __syncthreads();
    float inv[4];
#pragma unroll
    for (int hh = 0; hh < 4; hh++)
        inv[hh] = 1.0f / (r2[(rbase + hh) * 2] + r2[(rbase + hh) * 2 + 1]);

    // write p to pS and attn
#pragma unroll
    for (int hh = 0; hh < 4; hh++) {
        float* arow = attn + ((size_t)(b * HH + h0 + hh) * LL + i0 + ti) * LL;
#pragma unroll
        for (int t = 0; t < 8; t++) {
            int j = t * 64 + jj;
            float p = s[hh][t] * inv[hh];
            pS[j * PST + rbase + hh] = p;
            arow[j] = p;
        }
    }

    // ---- phase 2: out_adj = sum_j p * adj_v, 16 tiles of 32 j ----
    const int ti2w = w >> 2;
    const int js   = w & 3;
    const int l2   = lane * 2;
    float2 o[8];
#pragma unroll
    for (int h = 0; h < 8; h++) { o[h].x = 0.f; o[h].y = 0.f; }

#pragma unroll 1
    for (int t2 = 0; t2 < 16; t2++) {
        if (t2 < 15) {
            const float* srcb = adjv_b + (size_t)(t2 + 1) * 32 * DD;
            const int base = OFF_BUF + ((t2 + 1) & 1) * SM2_TILE;
#pragma unroll
            for (int s2 = 0; s2 < 4; s2++) {
                int f = tid + s2 * NTHR;
                int d4 = f & 15, jx = (f >> 4) & 31, tq = f >> 9;
                cpa16(smemU + (uint32_t)(base + (tq * 32 + jx) * 64 + d4 * 4) * 4,
                      srcb + (size_t)tq * (LL * DD) + (size_t)jx * DD + d4 * 4);
            }
            CP_COMMIT;
            CP_WAIT1;
        } else {
            CP_WAIT0;
        }
        __syncthreads();

        const float* pb = sm + OFF_BUF + (t2 & 1) * SM2_TILE;
#pragma unroll
        for (int x = 0; x < 8; x++) {
            int jj2 = js * 8 + x;
            int j   = t2 * 32 + jj2;
            float2 av = *reinterpret_cast<const float2*>(pb + (ti2w * 32 + jj2) * 64 + l2);
            float4 pA = *reinterpret_cast<const float4*>(pS + j * PST + ti2w * 8);
            float4 pB = *reinterpret_cast<const float4*>(pS + j * PST + ti2w * 8 + 4);
            o[0].x += pA.x * av.x; o[0].y += pA.x * av.y;
            o[1].x += pA.y * av.x; o[1].y += pA.y * av.y;
            o[2].x += pA.z * av.x; o[2].y += pA.z * av.y;
            o[3].x += pA.w * av.x; o[3].y += pA.w * av.y;
            o[4].x += pB.x * av.x; o[4].y += pB.x * av.y;
            o[5].x += pB.y * av.x; o[5].y += pB.y * av.y;
            o[6].x += pB.z * av.x; o[6].y += pB.z * av.y;
            o[7].x += pB.w * av.x; o[7].y += pB.w * av.y;
        }
        __syncthreads();
    }

    // reduce 4 j-splits via smem (overlay on dead buffer 0 region)
    float* ored = sm + OFF_BUF;   // [4 js][32 rows][64 d] = 8192 floats
#pragma unroll
    for (int h = 0; h < 8; h++)
        *reinterpret_cast<float2*>(ored + ((js * 32 + ti2w * 8 + h) * 64) + l2) = o[h];
    __syncthreads();
    {
        int row = tid >> 4, d4 = tid & 15;
        float4 aa = reinterpret_cast<const float4*>(ored + (0 * 32 + row) * 64)[d4];
        float4 bb = reinterpret_cast<const float4*>(ored + (1 * 32 + row) * 64)[d4];
        float4 cc = reinterpret_cast<const float4*>(ored + (2 * 32 + row) * 64)[d4];
        float4 dd = reinterpret_cast<const float4*>(ored + (3 * 32 + row) * 64)[d4];
        float4 r;
        r.x = aa.x + bb.x + cc.x + dd.x;
        r.y = aa.y + bb.y + cc.y + dd.y;
        r.z = aa.z + bb.z + cc.z + dd.z;
        r.w = aa.w + bb.w + cc.w + dd.w;
        int tio = row / HH, h = row % HH;
        *reinterpret_cast<float4*>(
            &out[((size_t)(b * HH + h) * LL + i0 + tio) * DD + d4 * 4]) = r;
    }
}

// =====================================================================
// Kernel 3: out += attn @ v.  grid 256 = 16 bh x 8... (16 i-tiles of 32)
// 256 thr; warp = 32 d-lane pairs, ty picks 4 i rows. cp.async dbl-buffered.
// =====================================================================
__global__ void __launch_bounds__(256, 4)
av_kernel(const float* __restrict__ v, float* __restrict__ out,
          const float* __restrict__ attn_ext, int write_ext)
{
    __shared__ float aS[2][32 * 32];   // [i][j]
    __shared__ float vS[2][32 * 64];   // [j][d]
    const float* attn = write_ext ? attn_ext : g_attn_fb;

    const int bid = blockIdx.x;
    const int bh  = bid >> 4;
    const int i0  = (bid & 15) * 32;
    const int tid = threadIdx.x;
    const uint32_t aU = (uint32_t)__cvta_generic_to_shared(&aS[0][0]);
    const uint32_t vU = (uint32_t)__cvta_generic_to_shared(&vS[0][0]);

    const float* ab = attn + ((size_t)bh * LL + i0) * LL;
    const float* vb = v + (size_t)bh * LL * DD;

    // stage tile 0
    {
        int i = tid >> 3, c = tid & 7;
        cpa16(aU + (uint32_t)(i * 32 + c * 4) * 4, ab + (size_t)i * LL + c * 4);
#pragma unroll
        for (int s2 = 0; s2 < 2; s2++) {
            int f = tid + s2 * 256;
            int j = f >> 4, d4 = f & 15;
            cpa16(vU + (uint32_t)(j * 64 + d4 * 4) * 4, vb + (size_t)j * DD + d4 * 4);
        }
        CP_COMMIT;
    }

    const int ty = tid >> 5, tx = tid & 31;
    float2 o[4];
#pragma unroll
    for (int r = 0; r < 4; r++) { o[r].x = 0.f; o[r].y = 0.f; }

#pragma unroll 1
    for (int kt = 0; kt < 16; kt++) {
        if (kt < 15) {
            int j0 = (kt + 1) * 32;
            int bsel = (kt + 1) & 1;
            int i = tid >> 3, c = tid & 7;
            cpa16(aU + (uint32_t)(bsel * 1024 + i * 32 + c * 4) * 4,
                  ab + (size_t)i * LL + j0 + c * 4);
#pragma unroll
            for (int s2 = 0; s2 < 2; s2++) {
                int f = tid + s2 * 256;
                int j = f >> 4, d4 = f & 15;
                cpa16(vU + (uint32_t)(bsel * 2048 + j * 64 + d4 * 4) * 4,
                      vb + (size_t)(j0 + j) * DD + d4 * 4);
            }
            CP_COMMIT;
            CP_WAIT1;
        } else {
            CP_WAIT0;
        }
        __syncthreads();

        const float* aT = &aS[kt & 1][0];
        const float* vT = &vS[kt & 1][0];
#pragma unroll 4
        for (int j = 0; j < 32; j++) {
            float2 vv = *reinterpret_cast<const float2*>(vT + j * 64 + tx * 2);
            float p0 = aT[(ty * 4 + 0) * 32 + j];
            float p1 = aT[(ty * 4 + 1) * 32 + j];
            float p2 = aT[(ty * 4 + 2) * 32 + j];
            float p3 = aT[(ty * 4 + 3) * 32 + j];
            o[0].x += p0 * vv.x; o[0].y += p0 * vv.y;
            o[1].x += p1 * vv.x; o[1].y += p1 * vv.y;
            o[2].x += p2 * vv.x; o[2].y += p2 * vv.y;
            o[3].x += p3 * vv.x; o[3].y += p3 * vv.y;
        }
        __syncthreads();
    }

#pragma unroll
    for (int r = 0; r < 4; r++) {
        float2* op = reinterpret_cast<float2*>(
            &out[((size_t)bh * LL + i0 + ty * 4 + r) * DD + tx * 2]);
        float2 cur = *op;
        cur.x += o[r].x; cur.y += o[r].y;
        *op = cur;
    }
}

// =====================================================================
extern "C" void kernel_launch(void* const* d_in, const int* in_sizes, int n_in,
                              void* d_out, int out_size)
{
    const float* q    = (const float*)d_in[0];
    const float* k    = (const float*)d_in[1];
    const float* v    = (const float*)d_in[2];
    const float* adjk = (const float*)d_in[3];
    const float* adjv = (const float*)d_in[4];
    const int*   mask = (const int*)d_in[5];
    float* out = (float*)d_out;

    int write_attn = (out_size >= OUT_ELEMS + ATTN_ELEMS) ? 1 : 0;
    float* attn_ext = out + OUT_ELEMS;   // only dereferenced when write_attn

    cudaFuncSetAttribute(qk_kernel, cudaFuncAttributeMaxDynamicSharedMemorySize,
                         QK_SMEM_FLOATS * 4);
    cudaFuncSetAttribute(main_kernel, cudaFuncAttributeMaxDynamicSharedMemorySize,
                         MAIN_SMEM_FLOATS * 4);

    qk_kernel<<<256, 256, QK_SMEM_FLOATS * 4>>>(q, k);
    main_kernel<<<BB * (LL / TI), NTHR, MAIN_SMEM_FLOATS * 4>>>(
        q, adjk, adjv, mask, out, attn_ext, write_attn);
    av_kernel<<<256, 256>>>(v, out, attn_ext, write_attn);
}

// round 6
// speedup vs baseline: 3.8524x; 1.4153x over previous
#include <cuda_runtime.h>
#include <cstdint>

#define BB 2
#define HH 8
#define LL 512
#define DD 64
#define TI 4
#define NTHR 512
#define TEMPINV 0.125f

#define OUT_ELEMS  (BB*HH*LL*DD)
#define ATTN_ELEMS (BB*HH*LL*LL)

// 16 MB scratch for base scores qs@k^T ; 16 MB fallback attn buffer
__device__ float g_s0[ATTN_ELEMS];
__device__ float g_attn_fb[ATTN_ELEMS];

// ---------- main kernel smem layout (floats) ----------
#define OFF_QS   0                  // qs[4][8][64] = 2048
#define OFF_MK   2048               // 512
#define OFF_R1   2560               // 64
#define OFF_R2   2624               // 64
#define OFF_BUF  2688               // double buffers
#define SM1_TILE (4*64*68)          // 17408 (phase1 adjk tile, PAD 68)
#define SM2_TILE (4*64*64)          // 16384 (phase2 adjv tile, JT2=64)
#define MAIN_SMEM_FLOATS (OFF_BUF + 2*SM1_TILE)   // 37504 -> 150016 B

// ---------- PTX helpers ----------
__device__ __forceinline__ void cpa16(uint32_t dst, const void* src) {
    asm volatile("cp.async.cg.shared.global [%0], [%1], 16;" :: "r"(dst), "l"(src) : "memory");
}
#define CP_COMMIT asm volatile("cp.async.commit_group;" ::: "memory")
#define CP_WAIT1  asm volatile("cp.async.wait_group 1;" ::: "memory")
#define CP_WAIT0  asm volatile("cp.async.wait_group 0;" ::: "memory")

__device__ __forceinline__ void fma2(unsigned long long& d,
                                     unsigned long long a, unsigned long long b) {
    asm("fma.rn.f32x2 %0, %1, %2, %0;" : "+l"(d) : "l"(a), "l"(b));
}
__device__ __forceinline__ float hadd2(unsigned long long v) {
    float lo, hi;
    asm("mov.b64 {%0,%1}, %2;" : "=f"(lo), "=f"(hi) : "l"(v));
    return lo + hi;
}
__device__ __forceinline__ unsigned long long pack2(float lo, float hi) {
    unsigned long long r;
    asm("mov.b64 %0, {%1,%2};" : "=l"(r) : "f"(lo), "f"(hi));
    return r;
}
__device__ __forceinline__ void unpack2(float& lo, float& hi, unsigned long long v) {
    asm("mov.b64 {%0,%1}, %2;" : "=f"(lo), "=f"(hi) : "l"(v));
}
__device__ __forceinline__ float warp_max(float x) {
#pragma unroll
    for (int o = 16; o; o >>= 1) x = fmaxf(x, __shfl_xor_sync(0xffffffffu, x, o));
    return x;
}
__device__ __forceinline__ float warp_sum(float x) {
#pragma unroll
    for (int o = 16; o; o >>= 1) x += __shfl_xor_sync(0xffffffffu, x, o);
    return x;
}

// =====================================================================
// Kernel 1: QK base scores. g_s0[bh,i,j] = (q/8)[bh,i,:] . k[bh,j,:]
// grid 256 = 16 bh x (4 itile x 4 jtile of 128x128), 256 thr, 8x8 micro
// f32x2-packed inner product.
// =====================================================================
#define QK_PADI 132
#define QK_SMEM_FLOATS (2*64*QK_PADI)   // 16896 -> 67584 B

__global__ void __launch_bounds__(256, 2)
qk_kernel(const float* __restrict__ q, const float* __restrict__ k)
{
    extern __shared__ float smq[];
    float* qT = smq;                 // [64 d][132]
    float* kT = smq + 64 * QK_PADI;  // [64 d][132]
    const int bid = blockIdx.x;
    const int bh = bid >> 4;
    const int it = (bid >> 2) & 3, jt = bid & 3;
    const int i0 = it * 128, j0 = jt * 128;
    const int tid = threadIdx.x;

    const float* qb = q + ((size_t)bh * LL + i0) * DD;
    const float* kb = k + ((size_t)bh * LL + j0) * DD;
#pragma unroll
    for (int f = tid; f < 128 * 64; f += 256) {
        int i = f >> 6, d = f & 63;
        qT[d * QK_PADI + i] = qb[(size_t)i * DD + d] * TEMPINV;
        kT[d * QK_PADI + i] = kb[(size_t)i * DD + d];
    }
    __syncthreads();

    const int ty = tid >> 4, tx = tid & 15;
    const int il = ty * 8, jl = tx * 8;
    unsigned long long acc[8][4];
#pragma unroll
    for (int r = 0; r < 8; r++)
#pragma unroll
        for (int c = 0; c < 4; c++) acc[r][c] = 0ull;

#pragma unroll 4
    for (int d = 0; d < 64; d++) {
        float4 a0 = *reinterpret_cast<const float4*>(qT + d * QK_PADI + il);
        float4 a1 = *reinterpret_cast<const float4*>(qT + d * QK_PADI + il + 4);
        const ulonglong2* bp = reinterpret_cast<const ulonglong2*>(kT + d * QK_PADI + jl);
        ulonglong2 b01 = bp[0], b23 = bp[1];
        float a[8] = {a0.x,a0.y,a0.z,a0.w,a1.x,a1.y,a1.z,a1.w};
#pragma unroll
        for (int r = 0; r < 8; r++) {
            unsigned long long ar = pack2(a[r], a[r]);
            fma2(acc[r][0], ar, b01.x);
            fma2(acc[r][1], ar, b01.y);
            fma2(acc[r][2], ar, b23.x);
            fma2(acc[r][3], ar, b23.y);
        }
    }

#pragma unroll
    for (int r = 0; r < 8; r++) {
        float c[8];
#pragma unroll
        for (int c2 = 0; c2 < 4; c2++) unpack2(c[2*c2], c[2*c2+1], acc[r][c2]);
        float* dst = g_s0 + ((size_t)bh * LL + i0 + il + r) * LL + j0 + jl;
        float4 v0 = {c[0], c[1], c[2], c[3]};
        float4 v1 = {c[4], c[5], c[6], c[7]};
        *reinterpret_cast<float4*>(dst)     = v0;
        *reinterpret_cast<float4*>(dst + 4) = v1;
    }
}

// =====================================================================
// Kernel 2 (main): adj-score accumulation + softmax + adj_v weighted sum
// grid 256 = (b, i-tile of 4 rows), 512 thr
// =====================================================================
__global__ void __launch_bounds__(NTHR, 1)
main_kernel(const float* __restrict__ q, const float* __restrict__ adjk,
            const float* __restrict__ adjv, const int* __restrict__ mask,
            float* __restrict__ out, float* __restrict__ attn_ext, int write_ext)
{
    extern __shared__ float sm[];
    float* attn = write_ext ? attn_ext : g_attn_fb;

    const int bid  = blockIdx.x;
    const int b    = bid / (LL / TI);
    const int i0   = (bid % (LL / TI)) * TI;
    const int tid  = threadIdx.x;
    const int w    = tid >> 5;
    const int lane = tid & 31;

    float* qs = sm + OFF_QS;
    float* mk = sm + OFF_MK;
    float* r1 = sm + OFF_R1;
    float* r2 = sm + OFF_R2;
    const uint32_t smemU = (uint32_t)__cvta_generic_to_shared(sm);

    // ---- phase 0: qs (scaled q) + mask flags ----
    {
        int d4 = tid & 15, h = (tid >> 4) & 7, ti = tid >> 7;
        float4 val = *reinterpret_cast<const float4*>(
            &q[((size_t)(b * HH + h) * LL + i0 + ti) * DD + d4 * 4]);
        val.x *= TEMPINV; val.y *= TEMPINV; val.z *= TEMPINV; val.w *= TEMPINV;
        reinterpret_cast<float4*>(qs)[(ti * HH + h) * (DD / 4) + d4] = val;
        mk[tid] = (mask[b * LL + tid] != 0) ? 1.0f : 0.0f;
    }

    // warp mapping phase 1: ti, jh (j half of 64), hg (head group of 4)
    const int ti  = w >> 2;
    const int sub = w & 3;
    const int jh  = sub >> 1;
    const int hg  = sub & 1;
    const int h0  = hg * 4;
    const int jj  = jh * 32 + lane;          // 0..63 within tile
    const int rbase = ti * HH + h0;          // row 0..31

    const float* adjk_b = adjk + ((size_t)(b * LL + i0) * LL) * DD;
    const float* adjv_b = adjv + ((size_t)(b * LL + i0) * LL) * DD;

    // prologue: stage phase-1 tile 0
    {
        const float* srcb = adjk_b;
#pragma unroll
        for (int s2 = 0; s2 < 8; s2++) {
            int f = tid + s2 * NTHR;
            int d4 = f & 15, jjx = (f >> 4) & 63, ti2 = f >> 10;
            cpa16(smemU + (uint32_t)(OFF_BUF + (ti2 * 64 + jjx) * 68 + d4 * 4) * 4,
                  srcb + (size_t)ti2 * (LL * DD) + (size_t)jjx * DD + d4 * 4);
        }
        CP_COMMIT;
    }

    // init scores from g_s0
    float s[4][8];
#pragma unroll
    for (int hh = 0; hh < 4; hh++)
#pragma unroll
        for (int t = 0; t < 8; t++)
            s[hh][t] = g_s0[((size_t)(b * HH + h0 + hh) * LL + i0 + ti) * LL + t * 64 + jj];

    // ---- phase 1: 8 tiles of 64 j, double-buffered ----
#pragma unroll
    for (int t = 0; t < 8; t++) {
        if (t < 7) {
            const float* srcb = adjk_b + (size_t)(t + 1) * 64 * DD;
            const int base = OFF_BUF + ((t + 1) & 1) * SM1_TILE;
#pragma unroll
            for (int s2 = 0; s2 < 8; s2++) {
                int f = tid + s2 * NTHR;
                int d4 = f & 15, jjx = (f >> 4) & 63, ti2 = f >> 10;
                cpa16(smemU + (uint32_t)(base + (ti2 * 64 + jjx) * 68 + d4 * 4) * 4,
                      srcb + (size_t)ti2 * (LL * DD) + (size_t)jjx * DD + d4 * 4);
            }
            CP_COMMIT;
            CP_WAIT1;
        } else {
            CP_WAIT0;
        }
        __syncthreads();

        const float* bufp = sm + OFF_BUF + (t & 1) * SM1_TILE;
        const ulonglong2* ap = reinterpret_cast<const ulonglong2*>(bufp + (ti * 64 + jj) * 68);
        const ulonglong2* q0 = reinterpret_cast<const ulonglong2*>(qs + (rbase + 0) * DD);
        const ulonglong2* q1 = reinterpret_cast<const ulonglong2*>(qs + (rbase + 1) * DD);
        const ulonglong2* q2 = reinterpret_cast<const ulonglong2*>(qs + (rbase + 2) * DD);
        const ulonglong2* q3 = reinterpret_cast<const ulonglong2*>(qs + (rbase + 3) * DD);
        unsigned long long a0 = 0ull, a1 = 0ull, a2 = 0ull, a3 = 0ull;
#pragma unroll
        for (int d4 = 0; d4 < 16; d4++) {
            ulonglong2 ad = ap[d4];
            ulonglong2 v0 = q0[d4]; fma2(a0, v0.x, ad.x); fma2(a0, v0.y, ad.y);
            ulonglong2 v1 = q1[d4]; fma2(a1, v1.x, ad.x); fma2(a1, v1.y, ad.y);
            ulonglong2 v2 = q2[d4]; fma2(a2, v2.x, ad.x); fma2(a2, v2.y, ad.y);
            ulonglong2 v3 = q3[d4]; fma2(a3, v3.x, ad.x); fma2(a3, v3.y, ad.y);
        }
        s[0][t] += hadd2(a0); s[1][t] += hadd2(a1);
        s[2][t] += hadd2(a2); s[3][t] += hadd2(a3);
        __syncthreads();
    }

    // prologue: stage phase-2 tile 0 (JT2=64) into buffer 0 (dead after tile 6)
#pragma unroll
    for (int s2 = 0; s2 < 8; s2++) {
        int f = tid + s2 * NTHR;
        int d4 = f & 15, jx = (f >> 4) & 63, ti2 = f >> 10;
        cpa16(smemU + (uint32_t)(OFF_BUF + (ti2 * 64 + jx) * 64 + d4 * 4) * 4,
              adjv_b + (size_t)ti2 * (LL * DD) + (size_t)jx * DD + d4 * 4);
    }
    CP_COMMIT;

    // ---- softmax (mask -> max -> exp -> norm) ----
    float m[4] = {-3.4e38f, -3.4e38f, -3.4e38f, -3.4e38f};
#pragma unroll
    for (int t = 0; t < 8; t++) {
        bool live = mk[t * 64 + jj] != 0.0f;
#pragma unroll
        for (int hh = 0; hh < 4; hh++) {
            float x = live ? s[hh][t] : -10000.0f;
            s[hh][t] = x;
            m[hh] = fmaxf(m[hh], x);
        }
    }
#pragma unroll
    for (int hh = 0; hh < 4; hh++) m[hh] = warp_max(m[hh]);
    if (lane == 0) {
#pragma unroll
        for (int hh = 0; hh < 4; hh++) r1[(rbase + hh) * 2 + jh] = m[hh];
    }
    __syncthreads();
#pragma unroll
    for (int hh = 0; hh < 4; hh++)
        m[hh] = fmaxf(r1[(rbase + hh) * 2], r1[(rbase + hh) * 2 + 1]);

    float sum[4] = {0.f, 0.f, 0.f, 0.f};
#pragma unroll
    for (int t = 0; t < 8; t++)
#pragma unroll
        for (int hh = 0; hh < 4; hh++) {
            float e = __expf(s[hh][t] - m[hh]);
            s[hh][t] = e;
            sum[hh] += e;
        }
#pragma unroll
    for (int hh = 0; hh < 4; hh++) sum[hh] = warp_sum(sum[hh]);
    if (lane == 0) {
#pragma unroll
        for (int hh = 0; hh < 4; hh++) r2[(rbase + hh) * 2 + jh] = sum[hh];
    }
    __syncthreads();
    float inv[4];
#pragma unroll
    for (int hh = 0; hh < 4; hh++)
        inv[hh] = 1.0f / (r2[(rbase + hh) * 2] + r2[(rbase + hh) * 2 + 1]);

    // write p to attn (gmem only; phase 2 reads it back via L1/L2-hot LDG)
#pragma unroll
    for (int hh = 0; hh < 4; hh++) {
        float* arow = attn + ((size_t)(b * HH + h0 + hh) * LL + i0 + ti) * LL;
#pragma unroll
        for (int t = 0; t < 8; t++) {
            int j = t * 64 + jj;
            arow[j] = s[hh][t] * inv[hh];
        }
    }
    // make attn writes visible to all warps before phase-2 reads
    __syncthreads();

    // ---- phase 2: out_adj = sum_j p * adj_v, 8 tiles of 64 j ----
    const int ti2w = w >> 2;
    const int js   = w & 3;
    const int l2   = lane * 2;

    const float* arp[8];
#pragma unroll
    for (int r = 0; r < 8; r++)
        arp[r] = attn + ((size_t)(b * HH + r) * LL + i0 + ti2w) * LL;

    float2 o[8];
#pragma unroll
    for (int h = 0; h < 8; h++) { o[h].x = 0.f; o[h].y = 0.f; }

#pragma unroll 1
    for (int t2 = 0; t2 < 8; t2++) {
        if (t2 < 7) {
            const float* srcb = adjv_b + (size_t)(t2 + 1) * 64 * DD;
            const int base = OFF_BUF + ((t2 + 1) & 1) * SM2_TILE;
#pragma unroll
            for (int s2 = 0; s2 < 8; s2++) {
                int f = tid + s2 * NTHR;
                int d4 = f & 15, jx = (f >> 4) & 63, tq = f >> 10;
                cpa16(smemU + (uint32_t)(base + (tq * 64 + jx) * 64 + d4 * 4) * 4,
                      srcb + (size_t)tq * (LL * DD) + (size_t)jx * DD + d4 * 4);
            }
            CP_COMMIT;
            CP_WAIT1;
        } else {
            CP_WAIT0;
        }
        __syncthreads();

        const float* pb = sm + OFF_BUF + (t2 & 1) * SM2_TILE;
#pragma unroll
        for (int x4 = 0; x4 < 4; x4++) {
            const int jb = js * 16 + x4 * 4;
            const int j  = t2 * 64 + jb;
            float4 p[8];
#pragma unroll
            for (int r = 0; r < 8; r++)
                p[r] = *reinterpret_cast<const float4*>(arp[r] + j);
            float2 av0 = *reinterpret_cast<const float2*>(pb + (ti2w * 64 + jb + 0) * 64 + l2);
            float2 av1 = *reinterpret_cast<const float2*>(pb + (ti2w * 64 + jb + 1) * 64 + l2);
            float2 av2 = *reinterpret_cast<const float2*>(pb + (ti2w * 64 + jb + 2) * 64 + l2);
            float2 av3 = *reinterpret_cast<const float2*>(pb + (ti2w * 64 + jb + 3) * 64 + l2);
#pragma unroll
            for (int r = 0; r < 8; r++) {
                o[r].x += p[r].x * av0.x; o[r].y += p[r].x * av0.y;
                o[r].x += p[r].y * av1.x; o[r].y += p[r].y * av1.y;
                o[r].x += p[r].z * av2.x; o[r].y += p[r].z * av2.y;
                o[r].x += p[r].w * av3.x; o[r].y += p[r].w * av3.y;
            }
        }
        __syncthreads();
    }

    // reduce 4 j-splits via smem (overlay on dead buffer 0 region)
    float* ored = sm + OFF_BUF;   // [4 js][32 rows][64 d] = 8192 floats
#pragma unroll
    for (int h = 0; h < 8; h++)
        *reinterpret_cast<float2*>(ored + ((js * 32 + ti2w * 8 + h) * 64) + l2) = o[h];
    __syncthreads();
    {
        int row = tid >> 4, d4 = tid & 15;
        float4 aa = reinterpret_cast<const float4*>(ored + (0 * 32 + row) * 64)[d4];
        float4 bb = reinterpret_cast<const float4*>(ored + (1 * 32 + row) * 64)[d4];
        float4 cc = reinterpret_cast<const float4*>(ored + (2 * 32 + row) * 64)[d4];
        float4 dd = reinterpret_cast<const float4*>(ored + (3 * 32 + row) * 64)[d4];
        float4 r;
        r.x = aa.x + bb.x + cc.x + dd.x;
        r.y = aa.y + bb.y + cc.y + dd.y;
        r.z = aa.z + bb.z + cc.z + dd.z;
        r.w = aa.w + bb.w + cc.w + dd.w;
        int tio = row / HH, h = row % HH;
        *reinterpret_cast<float4*>(
            &out[((size_t)(b * HH + h) * LL + i0 + tio) * DD + d4 * 4]) = r;
    }
}

// =====================================================================
// Kernel 3: out += attn @ v.  grid 256 = 16 bh x 16 i-tiles of 32
// =====================================================================
__global__ void __launch_bounds__(256, 4)
av_kernel(const float* __restrict__ v, float* __restrict__ out,
          const float* __restrict__ attn_ext, int write_ext)
{
    __shared__ float aS[2][32 * 32];   // [i][j]
    __shared__ float vS[2][32 * 64];   // [j][d]
    const float* attn = write_ext ? attn_ext : g_attn_fb;

    const int bid = blockIdx.x;
    const int bh  = bid >> 4;
    const int i0  = (bid & 15) * 32;
    const int tid = threadIdx.x;
    const uint32_t aU = (uint32_t)__cvta_generic_to_shared(&aS[0][0]);
    const uint32_t vU = (uint32_t)__cvta_generic_to_shared(&vS[0][0]);

    const float* ab = attn + ((size_t)bh * LL + i0) * LL;
    const float* vb = v + (size_t)bh * LL * DD;

    // stage tile 0
    {
        int i = tid >> 3, c = tid & 7;
        cpa16(aU + (uint32_t)(i * 32 + c * 4) * 4, ab + (size_t)i * LL + c * 4);
#pragma unroll
        for (int s2 = 0; s2 < 2; s2++) {
            int f = tid + s2 * 256;
            int j = f >> 4, d4 = f & 15;
            cpa16(vU + (uint32_t)(j * 64 + d4 * 4) * 4, vb + (size_t)j * DD + d4 * 4);
        }
        CP_COMMIT;
    }

    const int ty = tid >> 5, tx = tid & 31;
    float2 o[4];
#pragma unroll
    for (int r = 0; r < 4; r++) { o[r].x = 0.f; o[r].y = 0.f; }

#pragma unroll 1
    for (int kt = 0; kt < 16; kt++) {
        if (kt < 15) {
            int j0 = (kt + 1) * 32;
            int bsel = (kt + 1) & 1;
            int i = tid >> 3, c = tid & 7;
            cpa16(aU + (uint32_t)(bsel * 1024 + i * 32 + c * 4) * 4,
                  ab + (size_t)i * LL + j0 + c * 4);
#pragma unroll
            for (int s2 = 0; s2 < 2; s2++) {
                int f = tid + s2 * 256;
                int j = f >> 4, d4 = f & 15;
                cpa16(vU + (uint32_t)(bsel * 2048 + j * 64 + d4 * 4) * 4,
                      vb + (size_t)(j0 + j) * DD + d4 * 4);
            }
            CP_COMMIT;
            CP_WAIT1;
        } else {
            CP_WAIT0;
        }
        __syncthreads();

        const float* aT = &aS[kt & 1][0];
        const float* vT = &vS[kt & 1][0];
#pragma unroll 4
        for (int j = 0; j < 32; j++) {
            float2 vv = *reinterpret_cast<const float2*>(vT + j * 64 + tx * 2);
            float p0 = aT[(ty * 4 + 0) * 32 + j];
            float p1 = aT[(ty * 4 + 1) * 32 + j];
            float p2 = aT[(ty * 4 + 2) * 32 + j];
            float p3 = aT[(ty * 4 + 3) * 32 + j];
            o[0].x += p0 * vv.x; o[0].y += p0 * vv.y;
            o[1].x += p1 * vv.x; o[1].y += p1 * vv.y;
            o[2].x += p2 * vv.x; o[2].y += p2 * vv.y;
            o[3].x += p3 * vv.x; o[3].y += p3 * vv.y;
        }
        __syncthreads();
    }

#pragma unroll
    for (int r = 0; r < 4; r++) {
        float2* op = reinterpret_cast<float2*>(
            &out[((size_t)bh * LL + i0 + ty * 4 + r) * DD + tx * 2]);
        float2 cur = *op;
        cur.x += o[r].x; cur.y += o[r].y;
        *op = cur;
    }
}

// =====================================================================
extern "C" void kernel_launch(void* const* d_in, const int* in_sizes, int n_in,
                              void* d_out, int out_size)
{
    const float* q    = (const float*)d_in[0];
    const float* k    = (const float*)d_in[1];
    const float* v    = (const float*)d_in[2];
    const float* adjk = (const float*)d_in[3];
    const float* adjv = (const float*)d_in[4];
    const int*   mask = (const int*)d_in[5];
    float* out = (float*)d_out;

    int write_attn = (out_size >= OUT_ELEMS + ATTN_ELEMS) ? 1 : 0;
    float* attn_ext = out + OUT_ELEMS;   // only dereferenced when write_attn

    cudaFuncSetAttribute(qk_kernel, cudaFuncAttributeMaxDynamicSharedMemorySize,
                         QK_SMEM_FLOATS * 4);
    cudaFuncSetAttribute(main_kernel, cudaFuncAttributeMaxDynamicSharedMemorySize,
                         MAIN_SMEM_FLOATS * 4);

    qk_kernel<<<256, 256, QK_SMEM_FLOATS * 4>>>(q, k);
    main_kernel<<<BB * (LL / TI), NTHR, MAIN_SMEM_FLOATS * 4>>>(
        q, adjk, adjv, mask, out, attn_ext, write_attn);
    av_kernel<<<256, 256>>>(v, out, attn_ext, write_attn);
}